// round 17
// baseline (speedup 1.0000x reference)
#include <cuda_runtime.h>
#include <cuda_fp16.h>
#include <math.h>
#include <stdint.h>

#define BB 8
#define DD 256
#define LL 4096
#define KK 4096
#define NN (BB * LL)
#define NB4 (NN / 32)
#define MARGIN_F 2.5e-3f
#define FCAP (NN / 4)

// ---------------- scratch ----------------------------------------------------
__device__ __half g_Wh[(size_t)KK * DD];   // fp16 of normalized W, [k][d]
__device__ float  g_Wn[(size_t)KK * DD];   // normalized W fp32 (recheck)
__device__ float  g_xf[(size_t)FCAP * DD]; // gathered flagged x rows
__device__ unsigned long long g_best[NN];
__device__ int    g_idx[NN];
__device__ int    g_hist[KK];
__device__ float  g_sse[NB4];
__device__ int    g_nflag;
__device__ int    g_flag[NN];

// ---------------- helpers ----------------------------------------------------
__device__ __forceinline__ uint32_t smem_u32(const void* p) {
    uint32_t a;
    asm("{ .reg .u64 t; cvta.to.shared.u64 t, %1; cvt.u32.u64 %0, t; }" : "=r"(a) : "l"(p));
    return a;
}
#define SWZ(o) ((o) ^ (((o) >> 3) & 0x70))

#define LDSM4(r0, r1, r2, r3, addr) \
    asm volatile("ldmatrix.sync.aligned.m8n8.x4.shared.b16 {%0,%1,%2,%3}, [%4];" \
        : "=r"(r0), "=r"(r1), "=r"(r2), "=r"(r3) : "r"(addr))

#define MMA16816(c, a0, a1, a2, a3, b0, b1) \
    asm volatile("mma.sync.aligned.m16n8k16.row.col.f32.f16.f16.f32 " \
        "{%0,%1,%2,%3}, {%4,%5,%6,%7}, {%8,%9}, {%0,%1,%2,%3};" \
        : "+f"((c)[0]), "+f"((c)[1]), "+f"((c)[2]), "+f"((c)[3]) \
        : "r"(a0), "r"(a1), "r"(a2), "r"(a3), "r"(b0), "r"(b1))

#define CPA16(dst, src) \
    asm volatile("cp.async.cg.shared.global [%0], [%1], 16;" :: "r"(dst), "l"(src))
#define CPC() asm volatile("cp.async.commit_group;" ::: "memory")
#define CPW1() asm volatile("cp.async.wait_group 1;" ::: "memory")
#define CPW0() asm volatile("cp.async.wait_group 0;" ::: "memory")

// smem: A 4 chunks x 16KB = 64KB, then B ring 3 x 16KB = 48KB  -> 112KB
// (B ring doubles as fp32 staging area for the in-kernel A prep)
#define A_OFF(kc) ((kc) * 16384)
#define B_OFF(buf) (65536 + (buf) * 16384)
#define STG_OFF 65536
#define STG_STRIDE 132        // floats per staged d-row (pad vs 128)
#define SMEM_TOT 114688

// ---------------- k1: zero accumulators + normalize W, fp16 ------------------
__global__ void k_normw(const float* __restrict__ w) {
    {   // folded k_zero
        int bid = blockIdx.x, tid = threadIdx.x;
        if (bid < 32) g_hist[bid * 128 + tid] = 0;
        if (bid == 32 && tid == 0) g_nflag = 0;
    }
    int code = blockIdx.x * 4 + (threadIdx.x >> 5);
    int lane = threadIdx.x & 31;
    const float* row = w + (size_t)code * DD;
    float v[8];
    float ss = 0.f;
#pragma unroll
    for (int j = 0; j < 8; j++) { v[j] = row[lane + 32 * j]; ss = fmaf(v[j], v[j], ss); }
#pragma unroll
    for (int o = 16; o > 0; o >>= 1) ss += __shfl_xor_sync(0xffffffffu, ss, o);
    float den = fmaxf(__fsqrt_rn(ss), 1e-12f);
#pragma unroll
    for (int j = 0; j < 8; j++) {
        float nv = __fdiv_rn(v[j], den);
        size_t off = (size_t)code * DD + lane + 32 * j;
        g_Wn[off] = nv;
        g_Wh[off] = __float2half_rn(nv);
    }
}

// ---------------- k3: fused x-prep + 1-pass fp16 GEMM + argmax ---------------
__global__ __launch_bounds__(256, 2) void k_mma(const float* __restrict__ x) {
    extern __shared__ char smc[];
    const uint32_t smb = smem_u32(smc);
    const int tid = threadIdx.x, lane = tid & 31, wid = tid >> 5;
    const int wm = wid >> 2, wn = wid & 3;     // warp grid 2(M) x 4(N)
    const int n0 = blockIdx.x * 128;
    const int b  = n0 >> 12;
    const int l0 = n0 & (LL - 1);

    // ======== in-kernel A prep: x fp32 [b][d][l] -> A fp16 [l][d] swizzled ====
    {
        const float* xb = x + (size_t)b * DD * LL + l0;
        const int cl = tid & 127;          // l index for convert
        const int dg = tid >> 7;           // 0..1 -> 16 d-pairs each
#pragma unroll 1
        for (int p = 0; p < 4; p++) {
#pragma unroll
            for (int t = 0; t < 8; t++) {
                int q = tid + t * 256;             // 0..2047 float4s
                int r = q >> 5, c4 = q & 31;
                uint32_t dst = smb + STG_OFF + (r * STG_STRIDE + c4 * 4) * 4;
                CPA16(dst, xb + (size_t)(p * 64 + r) * LL + c4 * 4);
            }
            CPC(); CPW0();
            __syncthreads();
            const uint32_t axc = (uint32_t)((cl & 7) * 16);
            const uint32_t arb = A_OFF(p) + cl * 128;
#pragma unroll
            for (int j = 0; j < 16; j++) {
                int dp = dg * 16 + j;
                float f0 = *(const float*)(smc + STG_OFF + ((2 * dp) * STG_STRIDE + cl) * 4);
                float f1 = *(const float*)(smc + STG_OFF + ((2 * dp + 1) * STG_STRIDE + cl) * 4);
                __half2 h = __floats2half2_rn(f0, f1);
                *(__half2*)(smc + arb + ((uint32_t)(dp * 4) ^ axc)) = h;
            }
            __syncthreads();
        }
    }

    // ---- B chunk loader ----
    auto load_b = [&](int buf, int g) {
        int code0 = (g >> 2) * 128, kc = g & 3;
#pragma unroll
        for (int t = 0; t < 4; t++) {
            int q = tid + t * 256;
            int row = q >> 3, seg = q & 7;
            uint32_t dst = smb + B_OFF(buf) + SWZ(row * 128 + seg * 16);
            CPA16(dst, g_Wh + (size_t)(code0 + row) * DD + kc * 64 + seg * 8);
        }
    };
    load_b(0, 0); CPC();
    load_b(1, 1); CPC();

    float acc[4][4][4];
    float rb1[8], rb2[8];
    int   ri[8];
#pragma unroll
    for (int s = 0; s < 8; s++) { rb1[s] = -3e38f; rb2[s] = -3e38f; ri[s] = 0; }

    const int arow  = wm * 64 + (lane & 15);
    const int acolb = (lane >> 4) * 16;
    const int brow  = wn * 32 + (lane & 7) + ((lane >> 4) & 1) * 8;
    const int bcolb = ((lane >> 3) & 1) * 16;

    const uint32_t axor = (uint32_t)((arow & 7) * 16);
    const uint32_t bxor = (uint32_t)((brow & 7) * 16);
    uint32_t aabs[4], brel[2];
#pragma unroll
    for (int mi = 0; mi < 4; mi++) aabs[mi] = smb + (uint32_t)((arow + mi * 16) * 128);
#pragma unroll
    for (int nj = 0; nj < 2; nj++) brel[nj] = (uint32_t)((brow + nj * 16) * 128);

    int buf = 0, nbuf = 2;
    for (int g = 0; g < 128; g++) {
        const int kc = g & 3, tile = g >> 2;
        CPW1();
        __syncthreads();

        if (kc == 0) {
#pragma unroll
            for (int mi = 0; mi < 4; mi++)
#pragma unroll
                for (int ni = 0; ni < 4; ni++)
#pragma unroll
                    for (int c = 0; c < 4; c++) acc[mi][ni][c] = 0.f;
        }

        const uint32_t akc = (uint32_t)A_OFF(kc);
        const uint32_t bbase = smb + (uint32_t)B_OFF(buf);

#pragma unroll
        for (int d0 = 0; d0 < 4; d0++) {
            uint32_t a[4][4], bh[2][4];
            const uint32_t acol = akc + (((uint32_t)(d0 * 32) + acolb) ^ axor);
            const uint32_t bcol = (((uint32_t)(d0 * 32) + bcolb) ^ bxor);
#pragma unroll
            for (int nj = 0; nj < 2; nj++)
                LDSM4(bh[nj][0], bh[nj][1], bh[nj][2], bh[nj][3], bbase + brel[nj] + bcol);
#pragma unroll
            for (int mi = 0; mi < 4; mi++)
                LDSM4(a[mi][0], a[mi][1], a[mi][2], a[mi][3], aabs[mi] + acol);
#pragma unroll
            for (int mi = 0; mi < 4; mi++)
#pragma unroll
                for (int ni = 0; ni < 4; ni++) {
                    int nj = ni >> 1, hhalf = (ni & 1) * 2;
                    MMA16816(acc[mi][ni], a[mi][0], a[mi][1], a[mi][2], a[mi][3],
                             bh[nj][hhalf], bh[nj][hhalf + 1]);
                }
        }

        if (g + 2 < 128) load_b(nbuf, g + 2);
        CPC();
        if (++buf == 3) buf = 0;
        if (++nbuf == 3) nbuf = 0;

        if (kc == 3) {
            int cbase = tile * 128 + wn * 32 + (lane & 3) * 2;
#pragma unroll
            for (int mi = 0; mi < 4; mi++)
#pragma unroll
                for (int ni = 0; ni < 4; ni++)
#pragma unroll
                    for (int c = 0; c < 4; c++) {
                        float v = acc[mi][ni][c];
                        int slot = mi * 2 + (c >> 1);
                        int code = cbase + ni * 8 + (c & 1);
                        if (v > rb1[slot]) { rb2[slot] = rb1[slot]; rb1[slot] = v; ri[slot] = code; }
                        else if (v > rb2[slot]) rb2[slot] = v;
                    }
        }
    }

    // quad merge (lanes sharing rows), lowest index wins ties
#pragma unroll
    for (int off = 1; off < 4; off <<= 1) {
#pragma unroll
        for (int s = 0; s < 8; s++) {
            float o1 = __shfl_xor_sync(0xffffffffu, rb1[s], off);
            float o2 = __shfl_xor_sync(0xffffffffu, rb2[s], off);
            int   oi = __shfl_xor_sync(0xffffffffu, ri[s], off);
            float nb2 = fmaxf(fminf(rb1[s], o1), fmaxf(rb2[s], o2));
            if (o1 > rb1[s] || (o1 == rb1[s] && oi < ri[s])) { rb1[s] = o1; ri[s] = oi; }
            rb2[s] = nb2;
        }
    }

    // cross-warp (wn) merge through smem (A region now dead)
    float* s_b1 = (float*)smc;                 // [4][128]
    float* s_b2 = (float*)(smc + 2048);
    int*   s_ix = (int*)(smc + 4096);
    __syncthreads();
    if ((lane & 3) == 0) {
#pragma unroll
        for (int s = 0; s < 8; s++) {
            int row = wm * 64 + (s >> 1) * 16 + (lane >> 2) + 8 * (s & 1);
            s_b1[wn * 128 + row] = rb1[s];
            s_b2[wn * 128 + row] = rb2[s];
            s_ix[wn * 128 + row] = ri[s];
        }
    }
    __syncthreads();
    if (tid < 128) {
        float B1 = -3e38f, B2 = -3e38f;
        int I = 0x7fffffff;
#pragma unroll
        for (int j = 0; j < 4; j++) {
            float b1 = s_b1[j * 128 + tid];
            float b2 = s_b2[j * 128 + tid];
            int   ix = s_ix[j * 128 + tid];
            if (b1 > B1 || (b1 == B1 && ix < I)) {
                B2 = fmaxf(B1, b2);
                B1 = b1; I = ix;
            } else {
                B2 = fmaxf(B2, b1);
            }
        }
        int n = n0 + tid;
        g_idx[n] = I;
        if (B1 - B2 < MARGIN_F) {
            int p = atomicAdd(&g_nflag, 1);
            if (p < FCAP) {
                g_flag[p] = n;
                g_best[n] = 0ull;
            }
        }
    }
}

// ---------------- k3b: gather flagged x rows (fp32, dense) -------------------
__global__ void k_xflag(const float* __restrict__ x) {
    int nf = g_nflag; if (nf > FCAP) nf = FCAP;
    for (int f = blockIdx.x; f < nf; f += gridDim.x) {
        int n = g_flag[f];
        int b = n >> 12, l = n & (LL - 1);
        g_xf[(size_t)f * DD + threadIdx.x] =
            x[(size_t)b * DD * LL + (size_t)threadIdx.x * LL + l];
    }
}

// ---------------- k3c: warp-autonomous code-parallel exact recheck -----------
// Warp = 4 codes x 8 lanes -> wv[32] per thread (NO spill; the R13/R15
// versions' wv[64] spilled to local and L1-thrashed every row iteration).
// Block = 8 warps = 32 codes; grid (128 x-blocks, 16 y-slices).
// COVERAGE: every warp loops the SAME row stream f = blockIdx.y step 16, so
// each row is checked by all 128 x 32 = 4096 codes (the R16 bug split rows
// across warps and only covered 512 codes/row).
// Merge: monotonic-key atomicMax guarded by a plain read (order-independent,
// deterministic; stale read only costs an extra atomic, never wrongness).
__global__ __launch_bounds__(256) void k_recheck2() {
    __shared__ float xbuf[8][DD];
    const int tid = threadIdx.x;
    const int wid = tid >> 5, lane = tid & 31;
    const int code = blockIdx.x * 32 + wid * 4 + (lane >> 3);
    const int l8 = lane & 7;
    int nf = g_nflag; if (nf > FCAP) nf = FCAP;
    if (nf == 0) return;

    float wv[32];
    const float4* wr = (const float4*)(g_Wn + (size_t)code * DD + l8 * 32);
#pragma unroll
    for (int j = 0; j < 8; j++) {
        float4 t = wr[j];
        wv[4 * j] = t.x; wv[4 * j + 1] = t.y; wv[4 * j + 2] = t.z; wv[4 * j + 3] = t.w;
    }

    float* xw = xbuf[wid];
    float4 pf0, pf1;
    if ((int)blockIdx.y < nf) {
        const float4* src = (const float4*)(g_xf + (size_t)blockIdx.y * DD);
        pf0 = __ldg(src + lane * 2);
        pf1 = __ldg(src + lane * 2 + 1);
    }
    for (int f = (int)blockIdx.y; f < nf; f += 16) {
        *(float4*)(xw + lane * 8)     = pf0;
        *(float4*)(xw + lane * 8 + 4) = pf1;
        __syncwarp();
        int fn = f + 16;
        if (fn < nf) {                                 // prefetch next row
            const float4* src = (const float4*)(g_xf + (size_t)fn * DD);
            pf0 = __ldg(src + lane * 2);
            pf1 = __ldg(src + lane * 2 + 1);
        }
        float s0 = 0.f, s1 = 0.f, s2 = 0.f, s3 = 0.f;
        const float4* xr = (const float4*)(xw + l8 * 32);
#pragma unroll
        for (int j = 0; j < 8; j += 4) {
            float4 ta = xr[j], tb = xr[j + 1], tc = xr[j + 2], td = xr[j + 3];
            s0 = fmaf(wv[4*j+0],  ta.x, s0); s0 = fmaf(wv[4*j+1],  ta.y, s0);
            s0 = fmaf(wv[4*j+2],  ta.z, s0); s0 = fmaf(wv[4*j+3],  ta.w, s0);
            s1 = fmaf(wv[4*j+4],  tb.x, s1); s1 = fmaf(wv[4*j+5],  tb.y, s1);
            s1 = fmaf(wv[4*j+6],  tb.z, s1); s1 = fmaf(wv[4*j+7],  tb.w, s1);
            s2 = fmaf(wv[4*j+8],  tc.x, s2); s2 = fmaf(wv[4*j+9],  tc.y, s2);
            s2 = fmaf(wv[4*j+10], tc.z, s2); s2 = fmaf(wv[4*j+11], tc.w, s2);
            s3 = fmaf(wv[4*j+12], td.x, s3); s3 = fmaf(wv[4*j+13], td.y, s3);
            s3 = fmaf(wv[4*j+14], td.z, s3); s3 = fmaf(wv[4*j+15], td.w, s3);
        }
        float s = (s0 + s1) + (s2 + s3);
        s += __shfl_xor_sync(0xffffffffu, s, 1);
        s += __shfl_xor_sync(0xffffffffu, s, 2);
        s += __shfl_xor_sync(0xffffffffu, s, 4);
        uint32_t bits = __float_as_uint(s);
        uint32_t u = (bits & 0x80000000u) ? ~bits : (bits | 0x80000000u);
        unsigned long long key = ((unsigned long long)u << 32) | (unsigned)(4095 - code);
        // max across the warp's 4 code-groups (lanes of a group share keys)
#pragma unroll
        for (int o = 8; o < 32; o <<= 1) {
            unsigned long long ok = __shfl_xor_sync(0xffffffffu, key, o);
            if (ok > key) key = ok;
        }
        if (lane == 0) {
            int n = g_flag[f];
            if (key > g_best[n]) atomicMax(&g_best[n], key);
        }
        __syncwarp();                                  // xw consumed; safe to refill
    }
}

// ---------------- k3d: write rechecked indices -------------------------------
__global__ void k_fixidx() {
    int nf = g_nflag; if (nf > FCAP) nf = FCAP;
    for (int f = blockIdx.x * blockDim.x + threadIdx.x; f < nf; f += blockDim.x * gridDim.x) {
        int n = g_flag[f];
        g_idx[n] = 4095 - (int)(g_best[n] & 0xFFFu);
    }
}

// ---------------- k4: gather, transposed out, SSE, histogram -----------------
__global__ void k_gather(const float* __restrict__ x, const float* __restrict__ w,
                         float* __restrict__ out) {
    __shared__ float ws[32][257];
    __shared__ int   sidx[32];
    __shared__ float warpsum[8];
    const int tid = threadIdx.x;
    const int n0  = blockIdx.x * 32;
    const int b   = n0 >> 12;
    const int l0  = n0 & (LL - 1);

    if (tid < 32) {
        int id = g_idx[n0 + tid];
        sidx[tid] = id;
        atomicAdd(&g_hist[id], 1);
    }
    __syncthreads();
#pragma unroll 4
    for (int it = 0; it < 32; it++)
        ws[it][tid] = w[(size_t)sidx[it] * DD + tid];
    __syncthreads();

    const int lane = tid & 31, wp = tid >> 5;
    const float* xb = x + (size_t)b * DD * LL + l0;
    float* ob = out + (size_t)b * DD * LL + l0;
    float acc = 0.f;
#pragma unroll 8
    for (int it = 0; it < 32; it++) {
        int d = wp + it * 8;
        float qv = ws[lane][d];
        float xv = xb[(size_t)d * LL + lane];
        float df = qv - xv;
        acc = fmaf(df, df, acc);
        ob[(size_t)d * LL + lane] = qv;
    }
#pragma unroll
    for (int o = 16; o > 0; o >>= 1) acc += __shfl_xor_sync(0xffffffffu, acc, o);
    if (lane == 0) warpsum[wp] = acc;
    __syncthreads();
    if (tid == 0) {
        float s = 0.f;
        for (int i = 0; i < 8; i++) s += warpsum[i];
        g_sse[blockIdx.x] = s;
    }
}

// ---------------- k5: scalars ------------------------------------------------
__global__ void k_finalize(float* __restrict__ out, int qsz) {
    __shared__ double red[256];
    const int tid = threadIdx.x;

    double s = 0.0;
    for (int i = tid; i < NB4; i += 256) s += (double)g_sse[i];
    red[tid] = s;
    __syncthreads();
    for (int o = 128; o > 0; o >>= 1) { if (tid < o) red[tid] += red[tid + o]; __syncthreads(); }
    double sse = red[0];
    __syncthreads();

    double pl = 0.0;
    for (int k = tid; k < KK; k += 256) {
        float p = (float)g_hist[k] / (float)NN;
        pl += (double)(p * logf(p + 1e-10f));
    }
    red[tid] = pl;
    __syncthreads();
    for (int o = 128; o > 0; o >>= 1) { if (tid < o) red[tid] += red[tid + o]; __syncthreads(); }

    if (tid == 0) {
        double loss = 1.25 * sse / (double)(NN * DD);
        out[qsz]     = (float)loss;
        out[qsz + 1] = expf(-(float)red[0]);
    }
}

// ---------------- launch -----------------------------------------------------
extern "C" void kernel_launch(void* const* d_in, const int* in_sizes, int n_in,
                              void* d_out, int out_size) {
    const float* x = (const float*)d_in[0];   // [8, 256, 4096]
    const float* w = (const float*)d_in[1];   // [4096, 256]
    float* out = (float*)d_out;

    cudaFuncSetAttribute(k_mma, cudaFuncAttributeMaxDynamicSharedMemorySize, SMEM_TOT);

    k_normw<<<KK / 4, 128>>>(w);
    k_mma<<<NN / 128, 256, SMEM_TOT>>>(x);
    k_xflag<<<512, 256>>>(x);
    dim3 rg(KK / 32, 16);
    k_recheck2<<<rg, 256>>>();
    k_fixidx<<<8, 256>>>();
    k_gather<<<NN / 32, 256>>>(x, w, out);
    k_finalize<<<1, 256>>>(out, out_size - 2);
}